// round 1
// baseline (speedup 1.0000x reference)
#include <cuda_runtime.h>

// ---------------------------------------------------------------------------
// Fused ValueNetwork kernel (fp32 baseline, fully fused per-CTA)
//
// B=16384 batch elements, N=20 tokens, D=13 features.
// Each CTA processes NB=6 batch elements = 120 token rows (padded to 128).
// All activations live in shared memory in transposed [feat][row] layout
// (row stride 132 floats to avoid bank conflicts). Weights are staged from
// global (L2-resident, ~382KB total) into a 200x64 SMEM chunk buffer.
// Compute: 4 rows x 4 cols register tile per thread, 512 threads.
// ---------------------------------------------------------------------------

#define NTOK 20
#define D_IN 13
#define NB 6
#define ROWS_VALID (NB * NTOK)   // 120
#define ROWS_PAD 128
#define RS 132                   // activation row stride in floats
#define NTHREADS 512

// shared memory layout (float offsets)
#define OFF_A    0
#define SZ_A     (150 * RS)          // 19800  (mid1 / t / a1)
#define OFF_H    (OFF_A + SZ_A)
#define SZ_H     (100 * RS)          // 13200  (X / h / a2)
#define OFF_F    (OFF_H + SZ_H)
#define SZ_F     (50 * RS)           // 6600   (f)
#define OFF_W    (OFF_F + SZ_F)
#define SZ_W     (200 * 64)          // 12800  (weight chunk)
#define OFF_BIAS (OFF_W + SZ_W)
#define SZ_BIAS  64
#define OFF_G    (OFF_BIAS + SZ_BIAS)
#define SZ_G     (NB * 100)          // 600    (g = mean h per batch)
#define OFF_GATT (OFF_G + SZ_G)
#define SZ_GATT  (NB * 64)           // 384    (g @ aw0[100:200] per chunk)
#define OFF_ATT  (OFF_GATT + SZ_GATT)
#define SZ_ATT   ROWS_PAD            // 128    (attention scalar per row)
#define OFF_J    (OFF_ATT + SZ_ATT)
#define SZ_J     (NB * 56)           // 336    (joint)
#define OFF_M3A  (OFF_J + SZ_J)
#define SZ_M3A   (NB * 150)          // 900
#define OFF_M3B  (OFF_M3A + SZ_M3A)
#define SZ_M3B   (NB * 100)          // 600
#define SMEM_FLOATS (OFF_M3B + SZ_M3B)
#define SMEM_BYTES  (SMEM_FLOATS * 4)   // 221,648 bytes < 227KB limit

extern __shared__ float g_smem[];

// Generic SMEM->SMEM fused linear layer: dst = act(src @ W + bias)
// src: [K][RS] transposed activations, dst: [M][RS].
// W: global, row-major (K, M). Weights staged in 64-output-column chunks.
// ATT variant: W has K+100 rows (aw0, K=200); rows [100,200) multiply the
// per-batch g vector (row-constant within a batch), precomputed into sGatt.
template <bool RELU, bool ATT>
__device__ __forceinline__ void stage_gemm(
    const float* __restrict__ src, float* __restrict__ dst,
    const int K, const int M,
    const float* __restrict__ W, const float* __restrict__ bias,
    float* __restrict__ sW, float* __restrict__ sBias,
    const float* __restrict__ sG, float* __restrict__ sGatt,
    const int tid, const int cg, const int r0)
{
    const int Kload = ATT ? (K + 100) : K;
    for (int j0 = 0; j0 < M; j0 += 64) {
        const int cols = min(64, M - j0);
        // stage weight chunk (zero-fill unused columns -> no NaN garbage)
        for (int idx = tid; idx < Kload * 64; idx += NTHREADS) {
            const int k = idx >> 6, c = idx & 63;
            sW[idx] = (c < cols) ? W[k * M + j0 + c] : 0.f;
        }
        if (tid < 64) sBias[tid] = (tid < cols) ? bias[j0 + tid] : 0.f;
        __syncthreads();

        if (ATT) {
            // gatt[b][c] = sum_k g[b][k] * W[100+k][j0+c]  (row-constant part)
            for (int idx = tid; idx < NB * 64; idx += NTHREADS) {
                const int b = idx >> 6, c = idx & 63;
                const float* gp = sG + b * 100;
                const float* wp = sW + 100 * 64 + c;
                float s = 0.f;
#pragma unroll 4
                for (int k2 = 0; k2 < 100; ++k2) s += gp[k2] * wp[k2 * 64];
                sGatt[idx] = s;
            }
            __syncthreads();
        }

        float acc[4][4];
#pragma unroll
        for (int i = 0; i < 4; ++i) {
            if (ATT) {
                int b = (r0 + i) / NTOK;
                if (b > NB - 1) b = NB - 1;   // padded rows -> clamp
#pragma unroll
                for (int j = 0; j < 4; ++j)
                    acc[i][j] = sBias[(cg << 2) + j] + sGatt[b * 64 + (cg << 2) + j];
            } else {
#pragma unroll
                for (int j = 0; j < 4; ++j)
                    acc[i][j] = sBias[(cg << 2) + j];
            }
        }

        const float* sp = src + r0;
        const float* wp = sW + (cg << 2);
#pragma unroll 4
        for (int k = 0; k < K; ++k) {
            const float4 xv = *(const float4*)(sp + k * RS);
            const float4 wv = *(const float4*)(wp + (k << 6));
            acc[0][0] += xv.x * wv.x; acc[0][1] += xv.x * wv.y;
            acc[0][2] += xv.x * wv.z; acc[0][3] += xv.x * wv.w;
            acc[1][0] += xv.y * wv.x; acc[1][1] += xv.y * wv.y;
            acc[1][2] += xv.y * wv.z; acc[1][3] += xv.y * wv.w;
            acc[2][0] += xv.z * wv.x; acc[2][1] += xv.z * wv.y;
            acc[2][2] += xv.z * wv.z; acc[2][3] += xv.z * wv.w;
            acc[3][0] += xv.w * wv.x; acc[3][1] += xv.w * wv.y;
            acc[3][2] += xv.w * wv.z; acc[3][3] += xv.w * wv.w;
        }

#pragma unroll
        for (int j = 0; j < 4; ++j) {
            const int c = (cg << 2) + j;
            if (c < cols) {
                float4 v;
                v.x = acc[0][j]; v.y = acc[1][j]; v.z = acc[2][j]; v.w = acc[3][j];
                if (RELU) {
                    v.x = fmaxf(v.x, 0.f); v.y = fmaxf(v.y, 0.f);
                    v.z = fmaxf(v.z, 0.f); v.w = fmaxf(v.w, 0.f);
                }
                *(float4*)(dst + (j0 + c) * RS + r0) = v;
            }
        }
        __syncthreads();
    }
}

// tiny per-batch FC for the m3 head: in [NB][K] compact, out [NB][M] compact
__device__ __forceinline__ void small_fc(
    const float* __restrict__ in, const int K,
    float* __restrict__ outp, const int M,
    const float* __restrict__ W, const float* __restrict__ bias,
    const bool relu, const int tid)
{
    for (int idx = tid; idx < NB * M; idx += NTHREADS) {
        const int b = idx / M, j = idx - b * M;
        const float* ip = in + b * K;
        float s = bias[j];
#pragma unroll 4
        for (int k = 0; k < K; ++k) s += ip[k] * W[k * M + j];
        outp[idx] = relu ? fmaxf(s, 0.f) : s;
    }
    __syncthreads();
}

__global__ __launch_bounds__(NTHREADS, 1)
void fused_value_net(
    const float* __restrict__ state,
    const float* __restrict__ m1w0, const float* __restrict__ m1b0,
    const float* __restrict__ m1w1, const float* __restrict__ m1b1,
    const float* __restrict__ m2w0, const float* __restrict__ m2b0,
    const float* __restrict__ m2w1, const float* __restrict__ m2b1,
    const float* __restrict__ aw0,  const float* __restrict__ ab0,
    const float* __restrict__ aw1,  const float* __restrict__ ab1,
    const float* __restrict__ aw2,  const float* __restrict__ ab2,
    const float* __restrict__ m3w0, const float* __restrict__ m3b0,
    const float* __restrict__ m3w1, const float* __restrict__ m3b1,
    const float* __restrict__ m3w2, const float* __restrict__ m3b2,
    const float* __restrict__ m3w3, const float* __restrict__ m3b3,
    float* __restrict__ out, const int Btot)
{
    float* sA    = g_smem + OFF_A;
    float* sH    = g_smem + OFF_H;
    float* sF    = g_smem + OFF_F;
    float* sW    = g_smem + OFF_W;
    float* sBias = g_smem + OFF_BIAS;
    float* sG    = g_smem + OFF_G;
    float* sGatt = g_smem + OFF_GATT;
    float* sAtt  = g_smem + OFF_ATT;
    float* sJ    = g_smem + OFF_J;
    float* sM3a  = g_smem + OFF_M3A;
    float* sM3b  = g_smem + OFF_M3B;

    const int tid = threadIdx.x;
    const int cg  = tid & 15;       // 16 col-groups x 4 cols = 64 cols
    const int rg  = tid >> 4;       // 32 row-groups x 4 rows = 128 rows
    const int r0  = rg << 2;
    const int ctaB0 = blockIdx.x * NB;

    // ---- load state X into sH as [d][row] (invalid rows -> 0) ----
    for (int idx = tid; idx < D_IN * ROWS_PAD; idx += NTHREADS) {
        const int r = idx & 127, d = idx >> 7;
        const int b = r / NTOK, n = r - b * NTOK;
        const int gb = ctaB0 + b;
        float v = 0.f;
        if (r < ROWS_VALID && gb < Btot)
            v = state[((long)gb * NTOK + n) * D_IN + d];
        sH[d * RS + r] = v;
    }
    __syncthreads();

    // ---- m1: 13 -> 150 -> 100 (relu, relu) ----
    stage_gemm<true, false>(sH, sA, D_IN, 150, m1w0, m1b0, sW, sBias, sG, sGatt, tid, cg, r0);
    stage_gemm<true, false>(sA, sH, 150, 100, m1w1, m1b1, sW, sBias, sG, sGatt, tid, cg, r0);

    // ---- g = mean_n h  (per batch) ----
    for (int idx = tid; idx < NB * 100; idx += NTHREADS) {
        const int b = idx / 100, k = idx - b * 100;
        const float* hp = sH + k * RS + b * NTOK;
        float s = 0.f;
#pragma unroll
        for (int n = 0; n < NTOK; ++n) s += hp[n];
        sG[idx] = s * (1.f / NTOK);
    }
    __syncthreads();

    // ---- m2: h -> 100 (relu) -> 50 (linear) ----
    stage_gemm<true,  false>(sH, sA, 100, 100, m2w0, m2b0, sW, sBias, sG, sGatt, tid, cg, r0);
    stage_gemm<false, false>(sA, sF, 100, 50,  m2w1, m2b1, sW, sBias, sG, sGatt, tid, cg, r0);

    // ---- attention: a1 = relu([h, g] @ aw0 + ab0) ----
    stage_gemm<true, true >(sH, sA, 100, 100, aw0, ab0, sW, sBias, sG, sGatt, tid, cg, r0);
    // ---- a2 = relu(a1 @ aw1 + ab1) ----
    stage_gemm<true, false>(sA, sH, 100, 100, aw1, ab1, sW, sBias, sG, sGatt, tid, cg, r0);

    // ---- a = a2 @ aw2 + ab2  (scalar per row) ----
    if (tid < 100) sW[tid] = aw2[tid];
    __syncthreads();
    if (tid < ROWS_PAD) {
        float s = ab2[0];
#pragma unroll 4
        for (int k = 0; k < 100; ++k) s += sH[k * RS + tid] * sW[k];
        sAtt[tid] = s;
    }
    __syncthreads();

    // ---- weighted = sum_n f * a ; joint = [self_state, weighted] ----
    for (int idx = tid; idx < NB * 50; idx += NTHREADS) {
        const int b = idx / 50, c = idx - b * 50;
        const int base = b * NTOK;
        float s = 0.f;
#pragma unroll
        for (int n = 0; n < NTOK; ++n) s += sF[c * RS + base + n] * sAtt[base + n];
        sJ[b * 56 + 6 + c] = s;
    }
    if (tid < NB * 6) {
        const int b = tid / 6, d = tid - b * 6;
        const int gb = ctaB0 + b;
        sJ[b * 56 + d] = (gb < Btot) ? state[(long)gb * NTOK * D_IN + d] : 0.f;
    }
    __syncthreads();

    // ---- m3 head: 56 -> 150 -> 100 -> 100 -> 1 ----
    small_fc(sJ,   56,  sM3a, 150, m3w0, m3b0, true, tid);
    small_fc(sM3a, 150, sM3b, 100, m3w1, m3b1, true, tid);
    small_fc(sM3b, 100, sM3a, 100, m3w2, m3b2, true, tid);

    if (tid < NB) {
        const int gb = ctaB0 + tid;
        if (gb < Btot) {
            float s = m3b3[0];
#pragma unroll 4
            for (int k = 0; k < 100; ++k) s += sM3a[tid * 100 + k] * m3w3[k];
            out[gb] = s;
        }
    }
}

extern "C" void kernel_launch(void* const* d_in, const int* in_sizes, int n_in,
                              void* d_out, int out_size)
{
    const float* state = (const float*)d_in[0];
    const float* m1w0  = (const float*)d_in[1];
    const float* m1b0  = (const float*)d_in[2];
    const float* m1w1  = (const float*)d_in[3];
    const float* m1b1  = (const float*)d_in[4];
    const float* m2w0  = (const float*)d_in[5];
    const float* m2b0  = (const float*)d_in[6];
    const float* m2w1  = (const float*)d_in[7];
    const float* m2b1  = (const float*)d_in[8];
    const float* aw0   = (const float*)d_in[9];
    const float* ab0   = (const float*)d_in[10];
    const float* aw1   = (const float*)d_in[11];
    const float* ab1   = (const float*)d_in[12];
    const float* aw2   = (const float*)d_in[13];
    const float* ab2   = (const float*)d_in[14];
    const float* m3w0  = (const float*)d_in[15];
    const float* m3b0  = (const float*)d_in[16];
    const float* m3w1  = (const float*)d_in[17];
    const float* m3b1  = (const float*)d_in[18];
    const float* m3w2  = (const float*)d_in[19];
    const float* m3b2  = (const float*)d_in[20];
    const float* m3w3  = (const float*)d_in[21];
    const float* m3b3  = (const float*)d_in[22];
    float* out = (float*)d_out;

    const int Btot = in_sizes[0] / (NTOK * D_IN);

    cudaFuncSetAttribute(fused_value_net,
                         cudaFuncAttributeMaxDynamicSharedMemorySize, SMEM_BYTES);

    const int grid = (Btot + NB - 1) / NB;
    fused_value_net<<<grid, NTHREADS, SMEM_BYTES>>>(
        state,
        m1w0, m1b0, m1w1, m1b1,
        m2w0, m2b0, m2w1, m2b1,
        aw0, ab0, aw1, ab1, aw2, ab2,
        m3w0, m3b0, m3w1, m3b1, m3w2, m3b2, m3w3, m3b3,
        out, Btot);
}